// round 9
// baseline (speedup 1.0000x reference)
#include <cuda_runtime.h>

#define BATCH 64
#define SEQ   512
#define DIM   300
#define HID   600
#define G4    2400            // 4*HID
#define ROWS  (BATCH*SEQ)     // 32768

// persistent-kernel config
#define GRID_P 120
#define HALFG  60
#define NJ     10             // j-units per block
#define NCOL   40             // 4 gates * NJ columns
#define NT     480            // threads (15 warps)
#define KSPLIT 3              // 3 warp-aligned k-groups
#define GT     160            // threads per group (5 warps)
#define KSEG   200            // 600 / KSPLIT
#define ZPAD   44             // padded z row
#define NCELL  (NJ * BATCH)   // 640 gate cells per block

typedef unsigned long long u64;

// ---------------- packed f32x2 helpers ----------------
__device__ __forceinline__ void ffma2(u64& d, u64 a, u64 b) {
    asm("fma.rn.f32x2 %0, %1, %2, %0;" : "+l"(d) : "l"(a), "l"(b));
}
__device__ __forceinline__ u64 pack2(float lo, float hi) {
    u64 r; asm("mov.b64 %0, {%1, %2};" : "=l"(r) : "f"(lo), "f"(hi)); return r;
}
__device__ __forceinline__ void unpack2(u64 v, float& lo, float& hi) {
    asm("mov.b64 {%0, %1}, %2;" : "=f"(lo), "=f"(hi) : "l"(v));
}

// ---------------- fast gate math ----------------
__device__ __forceinline__ float fast_sigmoid(float x) {
    return __fdividef(1.f, 1.f + __expf(-x));
}
__device__ __forceinline__ float fast_tanh(float x) {
    float r; asm("tanh.approx.f32 %0, %1;" : "=f"(r) : "f"(x)); return r;
}

// ---------------- device scratch ----------------
__device__ float g_xw[(size_t)2 * ROWS * G4];   // [dir][row][gatecol]
__device__ float g_UP[2 * (size_t)HID * G4];    // [dir][k][blk*40 + gate*10 + jj]
__device__ float g_hT[2][2][HID][BATCH];        // [parity][dir][k][b]
__device__ float g_hsum[2 * BATCH * HID];
__device__ unsigned g_cnt2[2];
__device__ unsigned g_rel2[2];

// ---------------- init ----------------
__global__ void k_init() {
    int i = blockIdx.x * blockDim.x + threadIdx.x;
    float* p = &g_hT[0][0][0][0];
    if (i < 2 * 2 * HID * BATCH) p[i] = 0.f;
    if (i < 2) { g_cnt2[i] = 0u; g_rel2[i] = 0u; }
}

// ---------------- repack U: [k][gcol] -> per-block contiguous ----------------
__global__ void k_transpose(const float* __restrict__ Uf, const float* __restrict__ Ub) {
    int i = blockIdx.x * blockDim.x + threadIdx.x;   // over HID*G4
    if (i >= HID * G4) return;
    int k = i / G4, gcol = i % G4;
    int gate = gcol / HID, j = gcol % HID;
    int blk = j / NJ, jj = j % NJ;
    size_t dst = (size_t)k * G4 + blk * NCOL + gate * NJ + jj;
    g_UP[dst]                      = Uf[i];
    g_UP[(size_t)HID * G4 + dst]   = Ub[i];
}

// ---------------- input GEMM: xw = X @ W + b (FFMA2) ----------------
#define BM 128
#define BN 64
#define GBK 12
__global__ __launch_bounds__(256) void k_gemm(const float* __restrict__ X,
                       const float* __restrict__ Wf, const float* __restrict__ bf,
                       const float* __restrict__ Wb, const float* __restrict__ bb) {
    int dir = blockIdx.z;
    const float* W    = dir ? Wb : Wf;
    const float* bias = dir ? bb : bf;
    int m0 = blockIdx.y * BM;
    int n0 = blockIdx.x * BN;
    __shared__ __align__(16) float As[GBK][BM];
    __shared__ __align__(16) float Bs[GBK][BN];
    int tid = threadIdx.x;
    int tx = tid & 15, ty = tid >> 4;
    u64 acc2[4][4] = {};
    for (int k0 = 0; k0 < DIM; k0 += GBK) {
        #pragma unroll
        for (int l = 0; l < (BM * GBK) / 256; ++l) {
            int idx = tid + l * 256;
            int r = idx / GBK, kk = idx % GBK;
            As[kk][r] = X[(size_t)(m0 + r) * DIM + k0 + kk];
        }
        #pragma unroll
        for (int l = 0; l < (BN * GBK) / 256; ++l) {
            int idx = tid + l * 256;
            int kk = idx / BN, c = idx & (BN - 1);
            int col = n0 + c;
            Bs[kk][c] = (col < G4) ? W[(size_t)(k0 + kk) * G4 + col] : 0.f;
        }
        __syncthreads();
        #pragma unroll
        for (int kk = 0; kk < GBK; ++kk) {
            float4 a0 = *(const float4*)&As[kk][ty * 8];
            float4 a1 = *(const float4*)&As[kk][ty * 8 + 4];
            float4 b4 = *(const float4*)&Bs[kk][tx * 4];
            u64 ap[4] = {pack2(a0.x, a0.y), pack2(a0.z, a0.w),
                         pack2(a1.x, a1.y), pack2(a1.z, a1.w)};
            u64 bp[4] = {pack2(b4.x, b4.x), pack2(b4.y, b4.y),
                         pack2(b4.z, b4.z), pack2(b4.w, b4.w)};
            #pragma unroll
            for (int i = 0; i < 4; i++)
                #pragma unroll
                for (int j = 0; j < 4; j++)
                    ffma2(acc2[i][j], ap[i], bp[j]);
        }
        __syncthreads();
    }
    float* outp = g_xw + (size_t)dir * ROWS * G4;
    #pragma unroll
    for (int i = 0; i < 4; i++) {
        int row = m0 + ty * 8 + 2 * i;
        #pragma unroll
        for (int j = 0; j < 4; j++) {
            int col = n0 + tx * 4 + j;
            if (col < G4) {
                float lo, hi; unpack2(acc2[i][j], lo, hi);
                float bv = bias[col];
                outp[(size_t)row * G4 + col]       = lo + bv;
                outp[(size_t)(row + 1) * G4 + col] = hi + bv;
            }
        }
    }
}

// ---------------- xw prefetch for one (b, jj) cell ----------------
__device__ __forceinline__ void load_xw4(float* px, int s, int b, int jj,
                                         int dir, int j0, int L) {
    bool active = (dir == 0) ? (s < SEQ) : (s < L);
    if (!active) return;
    int trow = (dir == 0) ? s : (L - 1 - s);
    const float* xwr = g_xw + ((size_t)dir * ROWS + b * SEQ + trow) * G4 + (j0 + jj);
    px[0] = __ldg(xwr);
    px[1] = __ldg(xwr + HID);
    px[2] = __ldg(xwr + 2 * HID);
    px[3] = __ldg(xwr + 3 * HID);
}

// ---------------- gate math for one (b, jj) cell ----------------
__device__ __forceinline__ void gate_cell(const float* __restrict__ z_sh,
                                          const float* __restrict__ px,
                                          int b, int jj, int dir, int j0,
                                          int s, int L, int rp,
                                          float& cr, float& hs) {
    float z0 = 0.f, z1 = 0.f, z2 = 0.f, z3 = 0.f;
    #pragma unroll
    for (int p = 0; p < KSPLIT; p++) {
        const float* zb = z_sh + (p * 64 + b) * ZPAD;
        z0 += zb[jj];
        z1 += zb[NJ + jj];
        z2 += zb[2 * NJ + jj];
        z3 += zb[3 * NJ + jj];
    }
    bool active = (dir == 0) ? true : (s < L);
    if (!active) return;
    float ig = fast_sigmoid(z0 + px[0]);
    float fg = fast_sigmoid(z1 + px[1]);
    float gg = fast_tanh(z2 + px[2]);
    float og = fast_sigmoid(z3 + px[3]);
    cr = fg * cr + ig * gg;
    float h = og * fast_tanh(cr);
    __stcg(&g_hT[rp ^ 1][dir][j0 + jj][b], h);     // L2 write-through
    if (dir == 1 || s < L) hs += h;
}

// ---------------- persistent recurrence kernel ----------------
__global__ __launch_bounds__(NT, 1) void k_persist(const int* __restrict__ lengths) {
    extern __shared__ __align__(16) float smem[];
    float* h_sh = smem;                        // [HID][64] = 38400 f (153.6KB)
    float* z_sh = smem + HID * 64;             // [KSPLIT][64][ZPAD] (33.8KB)

    int tid = threadIdx.x;
    int bx  = blockIdx.x;
    int dir = (bx >= HALFG) ? 1 : 0;
    int blk = dir ? bx - HALFG : bx;
    int j0  = blk * NJ;

    // group mapping: 3 groups of 160 threads (5 warps each)
    int g  = tid / GT;            // 0..2
    int lr = tid % GT;
    int bb = (lr / 10) * 4;       // 16 b-groups of 4
    int cc = (lr % 10) * 4;       // 10 c-groups of 4

    // per-thread staging addresses (group g stages rows [g*KSEG, (g+1)*KSEG))
    unsigned h_dst = (unsigned)__cvta_generic_to_shared(h_sh) + (g * GT + lr) * 320;

    // U pointer for this block/dir (per-block contiguous layout)
    const float* UPd = g_UP + (size_t)dir * HID * G4 + blk * NCOL + cc;

    // gate-cell mapping: cell = jj*64 + b; thread owns cell tid and tid+NT (tid<160)
    int b0c  = tid & 63;
    int jj0c = tid >> 6;            // 0..7
    int b1c  = (tid + NT) & 63;
    int jj1c = (tid + NT) >> 6;     // 7..9 for tid<160
    int L0 = __ldg(&lengths[b0c]);
    int L1 = (tid < 160) ? __ldg(&lengths[b1c]) : 0;
    float cr0 = 0.f, cr1 = 0.f, hs0 = 0.f, hs1 = 0.f;

    float px0[4], px1[4], nx0[4], nx1[4];
    load_xw4(px0, 0, b0c, jj0c, dir, j0, L0);
    if (tid < 160) load_xw4(px1, 0, b1c, jj1c, dir, j0, L1);

    unsigned* cntp = &g_cnt2[dir];
    unsigned* relp = &g_rel2[dir];

    __syncthreads();

    for (int s = 0; s < SEQ; s++) {
        int rp = s & 1;

        // ---- group-local staging: group g copies its 51.2KB h piece ----
        {
            const char* src = (const char*)(&g_hT[rp][dir][0][0]) + (g * GT + lr) * 320;
            #pragma unroll
            for (int t = 0; t < 20; t++) {
                asm volatile("cp.async.cg.shared.global [%0], [%1], 16;"
                             :: "r"(h_dst + t * 16), "l"(src + t * 16));
            }
            asm volatile("cp.async.commit_group;" ::: "memory");
            asm volatile("cp.async.wait_group 0;" ::: "memory");
            asm volatile("bar.sync %0, %1;" :: "r"(g + 1), "r"(GT) : "memory");
        }

        // ---- matvec over this group's k-seg: h from smem, U via L1 ----
        const float* hp = h_sh + (g * KSEG) * 64 + bb;
        const float* up = UPd + (size_t)(g * KSEG) * G4;
        u64 acc2[2][4] = {};
        #pragma unroll 4
        for (int k = 0; k < KSEG; k++) {
            float4 h4 = *(const float4*)hp;  hp += 64;
            float4 u4 = __ldg((const float4*)up);  up += G4;
            u64 hpair[2] = {pack2(h4.x, h4.y), pack2(h4.z, h4.w)};
            u64 ub[4] = {pack2(u4.x, u4.x), pack2(u4.y, u4.y),
                         pack2(u4.z, u4.z), pack2(u4.w, u4.w)};
            #pragma unroll
            for (int i = 0; i < 2; i++)
                #pragma unroll
                for (int j = 0; j < 4; j++)
                    ffma2(acc2[i][j], hpair[i], ub[j]);
        }
        #pragma unroll
        for (int i = 0; i < 2; i++) {
            float* zr0 = z_sh + (g * 64 + bb + 2 * i) * ZPAD + cc;
            float* zr1 = zr0 + ZPAD;
            #pragma unroll
            for (int j = 0; j < 4; j++) {
                float lo, hi; unpack2(acc2[i][j], lo, hi);
                zr0[j] = lo; zr1[j] = hi;
            }
        }

        // ---- prefetch next step's xw (L1-resident) ----
        load_xw4(nx0, s + 1, b0c, jj0c, dir, j0, L0);
        if (tid < 160) load_xw4(nx1, s + 1, b1c, jj1c, dir, j0, L1);

        __syncthreads();

        // ---- gate math / state update ----
        gate_cell(z_sh, px0, b0c, jj0c, dir, j0, s, L0, rp, cr0, hs0);
        if (tid < 160) gate_cell(z_sh, px1, b1c, jj1c, dir, j0, s, L1, rp, cr1, hs1);
        #pragma unroll
        for (int q = 0; q < 4; q++) { px0[q] = nx0[q]; px1[q] = nx1[q]; }
        __syncthreads();   // all h .cg stores issued before arrival

        // ---- per-direction global barrier: scoped release/acquire ----
        if (tid == 0) {
            unsigned a;
            asm volatile("atom.release.gpu.global.add.u32 %0, [%1], 1;"
                         : "=r"(a) : "l"(cntp) : "memory");
            if (a + 1u == (unsigned)HALFG * (unsigned)(s + 1)) {
                asm volatile("st.release.gpu.global.u32 [%0], %1;"
                             :: "l"(relp), "r"((unsigned)(s + 1)) : "memory");
            } else {
                unsigned v;
                do {
                    asm volatile("ld.acquire.gpu.global.u32 %0, [%1];"
                                 : "=r"(v) : "l"(relp) : "memory");
                } while (v < (unsigned)(s + 1));
            }
        }
        __syncthreads();
    }

    // ---- write per-cell hsum to global ----
    g_hsum[dir * BATCH * HID + b0c * HID + j0 + jj0c] = hs0;
    if (tid < 160)
        g_hsum[dir * BATCH * HID + b1c * HID + j0 + jj1c] = hs1;
}

// ---------------- finalize: mean over T ----------------
__global__ void k_final(float* __restrict__ out) {
    int i = blockIdx.x * blockDim.x + threadIdx.x;
    if (i >= BATCH * 2 * HID) return;
    int b = i / (2 * HID), j = i % (2 * HID);
    float v = (j < HID) ? g_hsum[b * HID + j]
                        : g_hsum[BATCH * HID + b * HID + (j - HID)];
    out[i] = v * (1.0f / SEQ);
}

// ---------------- launch ----------------
extern "C" void kernel_launch(void* const* d_in, const int* in_sizes, int n_in,
                              void* d_out, int out_size) {
    const float *X = nullptr, *Wf = nullptr, *Uf = nullptr, *bf = nullptr;
    const float *Wb = nullptr, *Ub = nullptr, *bb = nullptr;
    const int* lengths = nullptr;
    int cW = 0, cU = 0, cb = 0;
    for (int i = 0; i < n_in; i++) {
        int s = in_sizes[i];
        if      (s == BATCH * SEQ * DIM) X = (const float*)d_in[i];
        else if (s == BATCH)             lengths = (const int*)d_in[i];
        else if (s == DIM * G4)   { if (cW++ == 0) Wf = (const float*)d_in[i]; else Wb = (const float*)d_in[i]; }
        else if (s == HID * G4)   { if (cU++ == 0) Uf = (const float*)d_in[i]; else Ub = (const float*)d_in[i]; }
        else if (s == G4)         { if (cb++ == 0) bf = (const float*)d_in[i]; else bb = (const float*)d_in[i]; }
    }

    static const int smem_bytes = (HID * 64 + KSPLIT * 64 * ZPAD) * 4;   // 187392
    cudaFuncSetAttribute(k_persist, cudaFuncAttributeMaxDynamicSharedMemorySize, smem_bytes);

    k_init<<<(2 * 2 * HID * BATCH + 255) / 256, 256>>>();
    k_transpose<<<(HID * G4 + 255) / 256, 256>>>(Uf, Ub);
    k_gemm<<<dim3((G4 + BN - 1) / BN, ROWS / BM, 2), 256>>>(X, Wf, bf, Wb, bb);
    k_persist<<<GRID_P, NT, smem_bytes>>>(lengths);
    k_final<<<(BATCH * 2 * HID + 255) / 256, 256>>>((float*)d_out);
}

// round 10
// speedup vs baseline: 1.2592x; 1.2592x over previous
#include <cuda_runtime.h>

#define BATCH 64
#define SEQ   512
#define DIM   300
#define HID   600
#define G4    2400            // 4*HID
#define ROWS  (BATCH*SEQ)     // 32768

// persistent-kernel config (R7 skeleton + chunked h staging)
#define GRID_P 120
#define HALFG  60
#define NJ     10             // j-units per block
#define NCOL   40             // 4 gates * NJ columns
#define NT     480            // threads (15 warps)
#define KSPLIT 6
#define ZPAD   42             // padded z row
#define KC     120            // h chunk rows
#define NCHUNK 5              // 600 / KC
#define KSUB   20             // KC / KSPLIT
#define CHUNKF (KC * 64)      // floats per chunk (7680)
#define CHUNKB (CHUNKF * 4)   // bytes per chunk (30720)

typedef unsigned long long u64;

// ---------------- packed f32x2 helpers ----------------
__device__ __forceinline__ void ffma2(u64& d, u64 a, u64 b) {
    asm("fma.rn.f32x2 %0, %1, %2, %0;" : "+l"(d) : "l"(a), "l"(b));
}
__device__ __forceinline__ u64 pack2(float lo, float hi) {
    u64 r; asm("mov.b64 %0, {%1, %2};" : "=l"(r) : "f"(lo), "f"(hi)); return r;
}
__device__ __forceinline__ void unpack2(u64 v, float& lo, float& hi) {
    asm("mov.b64 {%0, %1}, %2;" : "=f"(lo), "=f"(hi) : "l"(v));
}

// ---------------- fast gate math ----------------
__device__ __forceinline__ float fast_sigmoid(float x) {
    return __fdividef(1.f, 1.f + __expf(-x));
}
__device__ __forceinline__ float fast_tanh(float x) {
    float r; asm("tanh.approx.f32 %0, %1;" : "=f"(r) : "f"(x)); return r;
}

// ---------------- device scratch ----------------
__device__ float g_xw[(size_t)2 * ROWS * G4];   // [dir][row][gatecol]
__device__ float g_UT[2 * G4 * HID];            // [dir][gatecol][k]
__device__ float g_hT[2][2][HID][BATCH];        // [parity][dir][k][b]
__device__ float g_hsum[2 * BATCH * HID];
__device__ unsigned g_cnt2[2];
__device__ unsigned g_rel2[2];

// ---------------- init ----------------
__global__ void k_init() {
    int i = blockIdx.x * blockDim.x + threadIdx.x;
    float* p = &g_hT[0][0][0][0];
    if (i < 2 * 2 * HID * BATCH) p[i] = 0.f;
    if (i < 2) { g_cnt2[i] = 0u; g_rel2[i] = 0u; }
}

// ---------------- transpose U -> UT ----------------
__global__ void k_transpose(const float* __restrict__ Uf, const float* __restrict__ Ub) {
    int i = blockIdx.x * blockDim.x + threadIdx.x;
    if (i >= HID * G4) return;
    int k = i / G4, n = i % G4;
    g_UT[n * HID + k]            = Uf[i];
    g_UT[G4 * HID + n * HID + k] = Ub[i];
}

// ---------------- input GEMM: xw = X @ W + b (FFMA2) ----------------
#define BM 128
#define BN 64
#define GBK 12
__global__ __launch_bounds__(256) void k_gemm(const float* __restrict__ X,
                       const float* __restrict__ Wf, const float* __restrict__ bf,
                       const float* __restrict__ Wb, const float* __restrict__ bb) {
    int dir = blockIdx.z;
    const float* W    = dir ? Wb : Wf;
    const float* bias = dir ? bb : bf;
    int m0 = blockIdx.y * BM;
    int n0 = blockIdx.x * BN;
    __shared__ __align__(16) float As[GBK][BM];
    __shared__ __align__(16) float Bs[GBK][BN];
    int tid = threadIdx.x;
    int tx = tid & 15, ty = tid >> 4;
    u64 acc2[4][4] = {};
    for (int k0 = 0; k0 < DIM; k0 += GBK) {
        #pragma unroll
        for (int l = 0; l < (BM * GBK) / 256; ++l) {
            int idx = tid + l * 256;
            int r = idx / GBK, kk = idx % GBK;
            As[kk][r] = X[(size_t)(m0 + r) * DIM + k0 + kk];
        }
        #pragma unroll
        for (int l = 0; l < (BN * GBK) / 256; ++l) {
            int idx = tid + l * 256;
            int kk = idx / BN, c = idx & (BN - 1);
            int col = n0 + c;
            Bs[kk][c] = (col < G4) ? W[(size_t)(k0 + kk) * G4 + col] : 0.f;
        }
        __syncthreads();
        #pragma unroll
        for (int kk = 0; kk < GBK; ++kk) {
            float4 a0 = *(const float4*)&As[kk][ty * 8];
            float4 a1 = *(const float4*)&As[kk][ty * 8 + 4];
            float4 b4 = *(const float4*)&Bs[kk][tx * 4];
            u64 ap[4] = {pack2(a0.x, a0.y), pack2(a0.z, a0.w),
                         pack2(a1.x, a1.y), pack2(a1.z, a1.w)};
            u64 bp[4] = {pack2(b4.x, b4.x), pack2(b4.y, b4.y),
                         pack2(b4.z, b4.z), pack2(b4.w, b4.w)};
            #pragma unroll
            for (int i = 0; i < 4; i++)
                #pragma unroll
                for (int j = 0; j < 4; j++)
                    ffma2(acc2[i][j], ap[i], bp[j]);
        }
        __syncthreads();
    }
    float* outp = g_xw + (size_t)dir * ROWS * G4;
    #pragma unroll
    for (int i = 0; i < 4; i++) {
        int row = m0 + ty * 8 + 2 * i;
        #pragma unroll
        for (int j = 0; j < 4; j++) {
            int col = n0 + tx * 4 + j;
            if (col < G4) {
                float lo, hi; unpack2(acc2[i][j], lo, hi);
                float bv = bias[col];
                outp[(size_t)row * G4 + col]       = lo + bv;
                outp[(size_t)(row + 1) * G4 + col] = hi + bv;
            }
        }
    }
}

// ---------------- xw prefetch for one (b, jj) cell ----------------
__device__ __forceinline__ void load_xw4(float* px, int s, int b, int jj,
                                         int dir, int j0, int L) {
    bool active = (dir == 0) ? (s < SEQ) : (s < L);
    if (!active) return;
    int trow = (dir == 0) ? s : (L - 1 - s);
    const float* xwr = g_xw + ((size_t)dir * ROWS + b * SEQ + trow) * G4 + (j0 + jj);
    px[0] = __ldg(xwr);
    px[1] = __ldg(xwr + HID);
    px[2] = __ldg(xwr + 2 * HID);
    px[3] = __ldg(xwr + 3 * HID);
}

// ---------------- gate math for one (b, jj) cell ----------------
__device__ __forceinline__ void gate_cell(const float* __restrict__ z_sh,
                                          const float* __restrict__ px,
                                          int b, int jj, int dir, int j0,
                                          int s, int L, int rp,
                                          float& cr, float& hs) {
    float z0 = 0.f, z1 = 0.f, z2 = 0.f, z3 = 0.f;
    #pragma unroll
    for (int p = 0; p < KSPLIT; p++) {
        const float* zb = z_sh + (p * 64 + b) * ZPAD;
        z0 += zb[jj];
        z1 += zb[NJ + jj];
        z2 += zb[2 * NJ + jj];
        z3 += zb[3 * NJ + jj];
    }
    bool active = (dir == 0) ? true : (s < L);
    if (!active) return;
    float ig = fast_sigmoid(z0 + px[0]);
    float fg = fast_sigmoid(z1 + px[1]);
    float gg = fast_tanh(z2 + px[2]);
    float og = fast_sigmoid(z3 + px[3]);
    cr = fg * cr + ig * gg;
    float h = og * fast_tanh(cr);
    __stcg(&g_hT[rp ^ 1][dir][j0 + jj][b], h);     // L2 write-through
    if (dir == 1 || s < L) hs += h;
}

// ---------------- cp.async: stage one 64B slice of an h chunk per thread ----
__device__ __forceinline__ void stage_chunk(unsigned h_base, const char* hsrc,
                                            int ck, int tid) {
    unsigned dst = h_base + ((ck & 1) ? CHUNKB : 0) + tid * 64;
    const char* src = hsrc + (size_t)ck * CHUNKB + tid * 64;
    asm volatile("cp.async.cg.shared.global [%0], [%1], 16;" :: "r"(dst),      "l"(src));
    asm volatile("cp.async.cg.shared.global [%0], [%1], 16;" :: "r"(dst + 16), "l"(src + 16));
    asm volatile("cp.async.cg.shared.global [%0], [%1], 16;" :: "r"(dst + 32), "l"(src + 32));
    asm volatile("cp.async.cg.shared.global [%0], [%1], 16;" :: "r"(dst + 48), "l"(src + 48));
    asm volatile("cp.async.commit_group;" ::: "memory");
}

// ---------------- persistent recurrence kernel ----------------
__global__ __launch_bounds__(NT, 1) void k_persist(const int* __restrict__ lengths) {
    extern __shared__ __align__(16) float smem[];
    float* u_sh = smem;                            // [HID][NCOL] 24000 f
    float* z_sh = smem + HID * NCOL;               // [KSPLIT][64][ZPAD] 16128 f
    float* h_sh = z_sh + KSPLIT * 64 * ZPAD;       // [2][KC][64] 15360 f

    int tid = threadIdx.x;
    int bx  = blockIdx.x;
    int dir = (bx >= HALFG) ? 1 : 0;
    int j0  = (dir ? bx - HALFG : bx) * NJ;

    unsigned h_base = (unsigned)__cvta_generic_to_shared(h_sh);

    // load this block's U slice into SMEM (once)
    {
        const float* UT = g_UT + (size_t)dir * G4 * HID;
        for (int idx = tid; idx < NCOL * HID; idx += NT) {
            int c = idx / HID, k = idx % HID;
            int gcol = (c / NJ) * HID + j0 + (c % NJ);
            u_sh[k * NCOL + c] = UT[(size_t)gcol * HID + k];
        }
    }

    // compute mapping: KSPLIT k-groups x 8 b-groups(8) x 10 c-groups(4)
    int kh = tid / 80;
    int r  = tid % 80;
    int bb = (r / 10) * 8;
    int cc = (r % 10) * 4;

    // gate-cell mapping: cell = jj*64 + b; thread owns cell tid and tid+NT (tid<160)
    int b0c  = tid & 63;
    int jj0c = tid >> 6;            // 0..7
    int b1c  = (tid + NT) & 63;
    int jj1c = (tid + NT) >> 6;     // 7..9 for tid<160
    int L0 = __ldg(&lengths[b0c]);
    int L1 = (tid < 160) ? __ldg(&lengths[b1c]) : 0;
    float cr0 = 0.f, cr1 = 0.f, hs0 = 0.f, hs1 = 0.f;

    float px0[4], px1[4], nx0[4], nx1[4];
    load_xw4(px0, 0, b0c, jj0c, dir, j0, L0);
    if (tid < 160) load_xw4(px1, 0, b1c, jj1c, dir, j0, L1);

    unsigned* cntp = &g_cnt2[dir];
    unsigned* relp = &g_rel2[dir];

    __syncthreads();

    for (int s = 0; s < SEQ; s++) {
        int rp = s & 1;
        const char* hsrc = (const char*)(&g_hT[rp][dir][0][0]);

        // ---- prologue: stage chunk 0 ----
        stage_chunk(h_base, hsrc, 0, tid);
        asm volatile("cp.async.wait_group 0;" ::: "memory");
        __syncthreads();

        u64 acc2[4][4] = {};
        #pragma unroll
        for (int ck = 0; ck < NCHUNK; ck++) {
            if (ck < NCHUNK - 1)
                stage_chunk(h_base, hsrc, ck + 1, tid);

            // matvec over this chunk's k-subrange for group kh
            const float* hp = h_sh + ((ck & 1) ? CHUNKF : 0) + (kh * KSUB) * 64 + bb;
            const float* up = u_sh + (ck * KC + kh * KSUB) * NCOL + cc;
            #pragma unroll 5
            for (int kk = 0; kk < KSUB; kk++) {
                float4 ha = *(const float4*)hp;
                float4 hb = *(const float4*)(hp + 4);
                hp += 64;
                float4 u4 = *(const float4*)up;
                up += NCOL;
                u64 hpair[4] = {pack2(ha.x, ha.y), pack2(ha.z, ha.w),
                                pack2(hb.x, hb.y), pack2(hb.z, hb.w)};
                u64 ub[4] = {pack2(u4.x, u4.x), pack2(u4.y, u4.y),
                             pack2(u4.z, u4.z), pack2(u4.w, u4.w)};
                #pragma unroll
                for (int i = 0; i < 4; i++)
                    #pragma unroll
                    for (int j = 0; j < 4; j++)
                        ffma2(acc2[i][j], hpair[i], ub[j]);
            }

            if (ck == NCHUNK - 1) {
                // write z partials; prefetch next step's xw (L1-resident)
                #pragma unroll
                for (int i = 0; i < 4; i++) {
                    float* zr0 = z_sh + ((kh * 64) + bb + 2 * i) * ZPAD + cc;
                    float* zr1 = zr0 + ZPAD;
                    #pragma unroll
                    for (int j = 0; j < 4; j++) {
                        float lo, hi; unpack2(acc2[i][j], lo, hi);
                        zr0[j] = lo; zr1[j] = hi;
                    }
                }
                load_xw4(nx0, s + 1, b0c, jj0c, dir, j0, L0);
                if (tid < 160) load_xw4(nx1, s + 1, b1c, jj1c, dir, j0, L1);
            } else {
                asm volatile("cp.async.wait_group 0;" ::: "memory");
            }
            __syncthreads();
        }

        // ---- gate math / state update ----
        gate_cell(z_sh, px0, b0c, jj0c, dir, j0, s, L0, rp, cr0, hs0);
        if (tid < 160) gate_cell(z_sh, px1, b1c, jj1c, dir, j0, s, L1, rp, cr1, hs1);
        #pragma unroll
        for (int q = 0; q < 4; q++) { px0[q] = nx0[q]; px1[q] = nx1[q]; }
        __syncthreads();   // all h .cg stores issued before arrival

        // ---- per-direction global barrier: scoped release/acquire ----
        if (tid == 0) {
            unsigned a;
            asm volatile("atom.release.gpu.global.add.u32 %0, [%1], 1;"
                         : "=r"(a) : "l"(cntp) : "memory");
            if (a + 1u == (unsigned)HALFG * (unsigned)(s + 1)) {
                asm volatile("st.release.gpu.global.u32 [%0], %1;"
                             :: "l"(relp), "r"((unsigned)(s + 1)) : "memory");
            } else {
                unsigned v;
                do {
                    asm volatile("ld.acquire.gpu.global.u32 %0, [%1];"
                                 : "=r"(v) : "l"(relp) : "memory");
                } while (v < (unsigned)(s + 1));
            }
        }
        __syncthreads();
    }

    // ---- write per-cell hsum to global ----
    g_hsum[dir * BATCH * HID + b0c * HID + j0 + jj0c] = hs0;
    if (tid < 160)
        g_hsum[dir * BATCH * HID + b1c * HID + j0 + jj1c] = hs1;
}

// ---------------- finalize: mean over T ----------------
__global__ void k_final(float* __restrict__ out) {
    int i = blockIdx.x * blockDim.x + threadIdx.x;
    if (i >= BATCH * 2 * HID) return;
    int b = i / (2 * HID), j = i % (2 * HID);
    float v = (j < HID) ? g_hsum[b * HID + j]
                        : g_hsum[BATCH * HID + b * HID + (j - HID)];
    out[i] = v * (1.0f / SEQ);
}

// ---------------- launch ----------------
extern "C" void kernel_launch(void* const* d_in, const int* in_sizes, int n_in,
                              void* d_out, int out_size) {
    const float *X = nullptr, *Wf = nullptr, *Uf = nullptr, *bf = nullptr;
    const float *Wb = nullptr, *Ub = nullptr, *bb = nullptr;
    const int* lengths = nullptr;
    int cW = 0, cU = 0, cb = 0;
    for (int i = 0; i < n_in; i++) {
        int s = in_sizes[i];
        if      (s == BATCH * SEQ * DIM) X = (const float*)d_in[i];
        else if (s == BATCH)             lengths = (const int*)d_in[i];
        else if (s == DIM * G4)   { if (cW++ == 0) Wf = (const float*)d_in[i]; else Wb = (const float*)d_in[i]; }
        else if (s == HID * G4)   { if (cU++ == 0) Uf = (const float*)d_in[i]; else Ub = (const float*)d_in[i]; }
        else if (s == G4)         { if (cb++ == 0) bf = (const float*)d_in[i]; else bb = (const float*)d_in[i]; }
    }

    static const int smem_bytes =
        (HID * NCOL + KSPLIT * 64 * ZPAD + 2 * KC * 64) * 4;   // 221952
    cudaFuncSetAttribute(k_persist, cudaFuncAttributeMaxDynamicSharedMemorySize, smem_bytes);

    k_init<<<(2 * 2 * HID * BATCH + 255) / 256, 256>>>();
    k_transpose<<<(HID * G4 + 255) / 256, 256>>>(Uf, Ub);
    k_gemm<<<dim3((G4 + BN - 1) / BN, ROWS / BM, 2), 256>>>(X, Wf, bf, Wb, bb);
    k_persist<<<GRID_P, NT, smem_bytes>>>(lengths);
    k_final<<<(BATCH * 2 * HID + 255) / 256, 256>>>((float*)d_out);
}

// round 11
// speedup vs baseline: 1.2637x; 1.0036x over previous
#include <cuda_runtime.h>

#define BATCH 64
#define SEQ   512
#define DIM   300
#define HID   600
#define G4    2400            // 4*HID
#define ROWS  (BATCH*SEQ)     // 32768

// persistent-kernel config (R10 skeleton, dataflow flags instead of barrier)
#define GRID_P 120
#define HALFG  60
#define NJ     10             // j-units per block
#define NCOL   40             // 4 gates * NJ columns
#define NT     480            // threads (15 warps)
#define KSPLIT 6
#define ZPAD   42             // padded z row
#define KC     120            // h chunk rows
#define NCHUNK 5              // 600 / KC
#define KSUB   20             // KC / KSPLIT
#define CHUNKF (KC * 64)      // floats per chunk (7680)
#define CHUNKB (CHUNKF * 4)   // bytes per chunk (30720)

typedef unsigned long long u64;

// ---------------- packed f32x2 helpers ----------------
__device__ __forceinline__ void ffma2(u64& d, u64 a, u64 b) {
    asm("fma.rn.f32x2 %0, %1, %2, %0;" : "+l"(d) : "l"(a), "l"(b));
}
__device__ __forceinline__ u64 pack2(float lo, float hi) {
    u64 r; asm("mov.b64 %0, {%1, %2};" : "=l"(r) : "f"(lo), "f"(hi)); return r;
}
__device__ __forceinline__ void unpack2(u64 v, float& lo, float& hi) {
    asm("mov.b64 {%0, %1}, %2;" : "=f"(lo), "=f"(hi) : "l"(v));
}

// ---------------- fast gate math ----------------
__device__ __forceinline__ float fast_sigmoid(float x) {
    return __fdividef(1.f, 1.f + __expf(-x));
}
__device__ __forceinline__ float fast_tanh(float x) {
    float r; asm("tanh.approx.f32 %0, %1;" : "=f"(r) : "f"(x)); return r;
}

// ---------------- device scratch ----------------
__device__ float g_xw[(size_t)2 * ROWS * G4];   // [dir][row][gatecol]
__device__ float g_UT[2 * G4 * HID];            // [dir][gatecol][k]
__device__ float g_hT[2][2][HID][BATCH];        // [parity][dir][k][b]
__device__ float g_hsum[2 * BATCH * HID];
__device__ unsigned g_flag[2][64][32];          // [dir][blk][pad] completed-steps flag

// ---------------- init ----------------
__global__ void k_init() {
    int i = blockIdx.x * blockDim.x + threadIdx.x;
    float* p = &g_hT[0][0][0][0];
    if (i < 2 * 2 * HID * BATCH) p[i] = 0.f;
    if (i < 2 * 64 * 32) ((unsigned*)g_flag)[i] = 0u;
}

// ---------------- transpose U -> UT ----------------
__global__ void k_transpose(const float* __restrict__ Uf, const float* __restrict__ Ub) {
    int i = blockIdx.x * blockDim.x + threadIdx.x;
    if (i >= HID * G4) return;
    int k = i / G4, n = i % G4;
    g_UT[n * HID + k]            = Uf[i];
    g_UT[G4 * HID + n * HID + k] = Ub[i];
}

// ---------------- input GEMM: xw = X @ W + b (FFMA2) ----------------
#define BM 128
#define BN 64
#define GBK 12
__global__ __launch_bounds__(256) void k_gemm(const float* __restrict__ X,
                       const float* __restrict__ Wf, const float* __restrict__ bf,
                       const float* __restrict__ Wb, const float* __restrict__ bb) {
    int dir = blockIdx.z;
    const float* W    = dir ? Wb : Wf;
    const float* bias = dir ? bb : bf;
    int m0 = blockIdx.y * BM;
    int n0 = blockIdx.x * BN;
    __shared__ __align__(16) float As[GBK][BM];
    __shared__ __align__(16) float Bs[GBK][BN];
    int tid = threadIdx.x;
    int tx = tid & 15, ty = tid >> 4;
    u64 acc2[4][4] = {};
    for (int k0 = 0; k0 < DIM; k0 += GBK) {
        #pragma unroll
        for (int l = 0; l < (BM * GBK) / 256; ++l) {
            int idx = tid + l * 256;
            int r = idx / GBK, kk = idx % GBK;
            As[kk][r] = X[(size_t)(m0 + r) * DIM + k0 + kk];
        }
        #pragma unroll
        for (int l = 0; l < (BN * GBK) / 256; ++l) {
            int idx = tid + l * 256;
            int kk = idx / BN, c = idx & (BN - 1);
            int col = n0 + c;
            Bs[kk][c] = (col < G4) ? W[(size_t)(k0 + kk) * G4 + col] : 0.f;
        }
        __syncthreads();
        #pragma unroll
        for (int kk = 0; kk < GBK; ++kk) {
            float4 a0 = *(const float4*)&As[kk][ty * 8];
            float4 a1 = *(const float4*)&As[kk][ty * 8 + 4];
            float4 b4 = *(const float4*)&Bs[kk][tx * 4];
            u64 ap[4] = {pack2(a0.x, a0.y), pack2(a0.z, a0.w),
                         pack2(a1.x, a1.y), pack2(a1.z, a1.w)};
            u64 bp[4] = {pack2(b4.x, b4.x), pack2(b4.y, b4.y),
                         pack2(b4.z, b4.z), pack2(b4.w, b4.w)};
            #pragma unroll
            for (int i = 0; i < 4; i++)
                #pragma unroll
                for (int j = 0; j < 4; j++)
                    ffma2(acc2[i][j], ap[i], bp[j]);
        }
        __syncthreads();
    }
    float* outp = g_xw + (size_t)dir * ROWS * G4;
    #pragma unroll
    for (int i = 0; i < 4; i++) {
        int row = m0 + ty * 8 + 2 * i;
        #pragma unroll
        for (int j = 0; j < 4; j++) {
            int col = n0 + tx * 4 + j;
            if (col < G4) {
                float lo, hi; unpack2(acc2[i][j], lo, hi);
                float bv = bias[col];
                outp[(size_t)row * G4 + col]       = lo + bv;
                outp[(size_t)(row + 1) * G4 + col] = hi + bv;
            }
        }
    }
}

// ---------------- xw prefetch for one (b, jj) cell ----------------
__device__ __forceinline__ void load_xw4(float* px, int s, int b, int jj,
                                         int dir, int j0, int L) {
    bool active = (dir == 0) ? (s < SEQ) : (s < L);
    if (!active) return;
    int trow = (dir == 0) ? s : (L - 1 - s);
    const float* xwr = g_xw + ((size_t)dir * ROWS + b * SEQ + trow) * G4 + (j0 + jj);
    px[0] = __ldg(xwr);
    px[1] = __ldg(xwr + HID);
    px[2] = __ldg(xwr + 2 * HID);
    px[3] = __ldg(xwr + 3 * HID);
}

// ---------------- gate math for one (b, jj) cell ----------------
__device__ __forceinline__ void gate_cell(const float* __restrict__ z_sh,
                                          const float* __restrict__ px,
                                          int b, int jj, int dir, int j0,
                                          int s, int L, int rp,
                                          float& cr, float& hs) {
    float z0 = 0.f, z1 = 0.f, z2 = 0.f, z3 = 0.f;
    #pragma unroll
    for (int p = 0; p < KSPLIT; p++) {
        const float* zb = z_sh + (p * 64 + b) * ZPAD;
        z0 += zb[jj];
        z1 += zb[NJ + jj];
        z2 += zb[2 * NJ + jj];
        z3 += zb[3 * NJ + jj];
    }
    bool active = (dir == 0) ? true : (s < L);
    if (!active) return;
    float ig = fast_sigmoid(z0 + px[0]);
    float fg = fast_sigmoid(z1 + px[1]);
    float gg = fast_tanh(z2 + px[2]);
    float og = fast_sigmoid(z3 + px[3]);
    cr = fg * cr + ig * gg;
    float h = og * fast_tanh(cr);
    __stcg(&g_hT[rp ^ 1][dir][j0 + jj][b], h);     // L2 write-through
    if (dir == 1 || s < L) hs += h;
}

// ---------------- poll producer flag, then stage one 64B h slice ----------------
__device__ __forceinline__ void stage_chunk(unsigned h_base, const char* hsrc,
                                            int ck, int tid,
                                            const unsigned* flags, int myblk,
                                            unsigned tgt) {
    // this thread's 64B covers h-row ck*KC + tid/4; producer block = row / NJ
    int prod = (ck * KC + (tid >> 2)) / NJ;
    if (prod != myblk) {
        const unsigned* fp = flags + prod * 32;
        unsigned v;
        do {
            asm volatile("ld.acquire.gpu.global.u32 %0, [%1];"
                         : "=r"(v) : "l"(fp) : "memory");
        } while (v < tgt);
    }
    unsigned dst = h_base + ((ck & 1) ? CHUNKB : 0) + tid * 64;
    const char* src = hsrc + (size_t)ck * CHUNKB + tid * 64;
    asm volatile("cp.async.cg.shared.global [%0], [%1], 16;" :: "r"(dst),      "l"(src));
    asm volatile("cp.async.cg.shared.global [%0], [%1], 16;" :: "r"(dst + 16), "l"(src + 16));
    asm volatile("cp.async.cg.shared.global [%0], [%1], 16;" :: "r"(dst + 32), "l"(src + 32));
    asm volatile("cp.async.cg.shared.global [%0], [%1], 16;" :: "r"(dst + 48), "l"(src + 48));
    asm volatile("cp.async.commit_group;" ::: "memory");
}

// ---------------- persistent recurrence kernel ----------------
__global__ __launch_bounds__(NT, 1) void k_persist(const int* __restrict__ lengths) {
    extern __shared__ __align__(16) float smem[];
    float* u_sh = smem;                            // [HID][NCOL] 24000 f
    float* z_sh = smem + HID * NCOL;               // [KSPLIT][64][ZPAD] 16128 f
    float* h_sh = z_sh + KSPLIT * 64 * ZPAD;       // [2][KC][64] 15360 f

    int tid = threadIdx.x;
    int bx  = blockIdx.x;
    int dir = (bx >= HALFG) ? 1 : 0;
    int blk = dir ? bx - HALFG : bx;
    int j0  = blk * NJ;

    unsigned h_base = (unsigned)__cvta_generic_to_shared(h_sh);
    const unsigned* flags = &g_flag[dir][0][0];

    // load this block's U slice into SMEM (once)
    {
        const float* UT = g_UT + (size_t)dir * G4 * HID;
        for (int idx = tid; idx < NCOL * HID; idx += NT) {
            int c = idx / HID, k = idx % HID;
            int gcol = (c / NJ) * HID + j0 + (c % NJ);
            u_sh[k * NCOL + c] = UT[(size_t)gcol * HID + k];
        }
    }

    // compute mapping: KSPLIT k-groups x 8 b-groups(8) x 10 c-groups(4)
    int kh = tid / 80;
    int r  = tid % 80;
    int bb = (r / 10) * 8;
    int cc = (r % 10) * 4;

    // gate-cell mapping: cell = jj*64 + b; thread owns cell tid and tid+NT (tid<160)
    int b0c  = tid & 63;
    int jj0c = tid >> 6;            // 0..7
    int b1c  = (tid + NT) & 63;
    int jj1c = (tid + NT) >> 6;     // 7..9 for tid<160
    int L0 = __ldg(&lengths[b0c]);
    int L1 = (tid < 160) ? __ldg(&lengths[b1c]) : 0;
    float cr0 = 0.f, cr1 = 0.f, hs0 = 0.f, hs1 = 0.f;

    float px0[4], px1[4], nx0[4], nx1[4];
    load_xw4(px0, 0, b0c, jj0c, dir, j0, L0);
    if (tid < 160) load_xw4(px1, 0, b1c, jj1c, dir, j0, L1);

    __syncthreads();

    for (int s = 0; s < SEQ; s++) {
        int rp = s & 1;
        const char* hsrc = (const char*)(&g_hT[rp][dir][0][0]);
        unsigned tgt = (unsigned)s;            // need producers' completed-steps >= s

        // ---- prologue: poll + stage chunk 0 ----
        stage_chunk(h_base, hsrc, 0, tid, flags, blk, tgt);
        asm volatile("cp.async.wait_group 0;" ::: "memory");
        __syncthreads();

        u64 acc2[4][4] = {};
        #pragma unroll
        for (int ck = 0; ck < NCHUNK; ck++) {
            if (ck < NCHUNK - 1)
                stage_chunk(h_base, hsrc, ck + 1, tid, flags, blk, tgt);

            // matvec over this chunk's k-subrange for group kh
            const float* hp = h_sh + ((ck & 1) ? CHUNKF : 0) + (kh * KSUB) * 64 + bb;
            const float* up = u_sh + (ck * KC + kh * KSUB) * NCOL + cc;
            #pragma unroll 5
            for (int kk = 0; kk < KSUB; kk++) {
                float4 ha = *(const float4*)hp;
                float4 hb = *(const float4*)(hp + 4);
                hp += 64;
                float4 u4 = *(const float4*)up;
                up += NCOL;
                u64 hpair[4] = {pack2(ha.x, ha.y), pack2(ha.z, ha.w),
                                pack2(hb.x, hb.y), pack2(hb.z, hb.w)};
                u64 ub[4] = {pack2(u4.x, u4.x), pack2(u4.y, u4.y),
                             pack2(u4.z, u4.z), pack2(u4.w, u4.w)};
                #pragma unroll
                for (int i = 0; i < 4; i++)
                    #pragma unroll
                    for (int j = 0; j < 4; j++)
                        ffma2(acc2[i][j], hpair[i], ub[j]);
            }

            if (ck == NCHUNK - 1) {
                // write z partials; prefetch next step's xw (L1-resident)
                #pragma unroll
                for (int i = 0; i < 4; i++) {
                    float* zr0 = z_sh + ((kh * 64) + bb + 2 * i) * ZPAD + cc;
                    float* zr1 = zr0 + ZPAD;
                    #pragma unroll
                    for (int j = 0; j < 4; j++) {
                        float lo, hi; unpack2(acc2[i][j], lo, hi);
                        zr0[j] = lo; zr1[j] = hi;
                    }
                }
                load_xw4(nx0, s + 1, b0c, jj0c, dir, j0, L0);
                if (tid < 160) load_xw4(nx1, s + 1, b1c, jj1c, dir, j0, L1);
            } else {
                asm volatile("cp.async.wait_group 0;" ::: "memory");
            }
            __syncthreads();
        }

        // ---- gate math / state update ----
        gate_cell(z_sh, px0, b0c, jj0c, dir, j0, s, L0, rp, cr0, hs0);
        if (tid < 160) gate_cell(z_sh, px1, b1c, jj1c, dir, j0, s, L1, rp, cr1, hs1);
        #pragma unroll
        for (int q = 0; q < 4; q++) { px0[q] = nx0[q]; px1[q] = nx1[q]; }
        __syncthreads();   // h .cg stores of all threads ordered before flag store

        // ---- publish: this block completed step s ----
        if (tid == 0) {
            asm volatile("st.release.gpu.global.u32 [%0], %1;"
                         :: "l"(&g_flag[dir][blk][0]), "r"((unsigned)(s + 1)) : "memory");
        }
    }

    // ---- write per-cell hsum to global ----
    g_hsum[dir * BATCH * HID + b0c * HID + j0 + jj0c] = hs0;
    if (tid < 160)
        g_hsum[dir * BATCH * HID + b1c * HID + j0 + jj1c] = hs1;
}

// ---------------- finalize: mean over T ----------------
__global__ void k_final(float* __restrict__ out) {
    int i = blockIdx.x * blockDim.x + threadIdx.x;
    if (i >= BATCH * 2 * HID) return;
    int b = i / (2 * HID), j = i % (2 * HID);
    float v = (j < HID) ? g_hsum[b * HID + j]
                        : g_hsum[BATCH * HID + b * HID + (j - HID)];
    out[i] = v * (1.0f / SEQ);
}

// ---------------- launch ----------------
extern "C" void kernel_launch(void* const* d_in, const int* in_sizes, int n_in,
                              void* d_out, int out_size) {
    const float *X = nullptr, *Wf = nullptr, *Uf = nullptr, *bf = nullptr;
    const float *Wb = nullptr, *Ub = nullptr, *bb = nullptr;
    const int* lengths = nullptr;
    int cW = 0, cU = 0, cb = 0;
    for (int i = 0; i < n_in; i++) {
        int s = in_sizes[i];
        if      (s == BATCH * SEQ * DIM) X = (const float*)d_in[i];
        else if (s == BATCH)             lengths = (const int*)d_in[i];
        else if (s == DIM * G4)   { if (cW++ == 0) Wf = (const float*)d_in[i]; else Wb = (const float*)d_in[i]; }
        else if (s == HID * G4)   { if (cU++ == 0) Uf = (const float*)d_in[i]; else Ub = (const float*)d_in[i]; }
        else if (s == G4)         { if (cb++ == 0) bf = (const float*)d_in[i]; else bb = (const float*)d_in[i]; }
    }

    static const int smem_bytes =
        (HID * NCOL + KSPLIT * 64 * ZPAD + 2 * KC * 64) * 4;   // 221952
    cudaFuncSetAttribute(k_persist, cudaFuncAttributeMaxDynamicSharedMemorySize, smem_bytes);

    k_init<<<(2 * 2 * HID * BATCH + 255) / 256, 256>>>();
    k_transpose<<<(HID * G4 + 255) / 256, 256>>>(Uf, Ub);
    k_gemm<<<dim3((G4 + BN - 1) / BN, ROWS / BM, 2), 256>>>(X, Wf, bf, Wb, bb);
    k_persist<<<GRID_P, NT, smem_bytes>>>(lengths);
    k_final<<<(BATCH * 2 * HID + 255) / 256, 256>>>((float*)d_out);
}

// round 12
// speedup vs baseline: 1.3653x; 1.0803x over previous
#include <cuda_runtime.h>

#define BATCH 64
#define SEQ   512
#define DIM   300
#define HID   600
#define G4    2400            // 4*HID
#define ROWS  (BATCH*SEQ)     // 32768

// persistent-kernel config (R11, unchanged)
#define GRID_P 120
#define HALFG  60
#define NJ     10
#define NCOL   40
#define NT     480
#define KSPLIT 6
#define ZPAD   42
#define KC     120
#define NCHUNK 5
#define KSUB   20
#define CHUNKF (KC * 64)
#define CHUNKB (CHUNKF * 4)

typedef unsigned long long u64;

// ---------------- packed f32x2 helpers ----------------
__device__ __forceinline__ void ffma2(u64& d, u64 a, u64 b) {
    asm("fma.rn.f32x2 %0, %1, %2, %0;" : "+l"(d) : "l"(a), "l"(b));
}
__device__ __forceinline__ u64 pack2(float lo, float hi) {
    u64 r; asm("mov.b64 %0, {%1, %2};" : "=l"(r) : "f"(lo), "f"(hi)); return r;
}
__device__ __forceinline__ void unpack2(u64 v, float& lo, float& hi) {
    asm("mov.b64 {%0, %1}, %2;" : "=f"(lo), "=f"(hi) : "l"(v));
}

// ---------------- fast gate math ----------------
__device__ __forceinline__ float fast_sigmoid(float x) {
    return __fdividef(1.f, 1.f + __expf(-x));
}
__device__ __forceinline__ float fast_tanh(float x) {
    float r; asm("tanh.approx.f32 %0, %1;" : "=f"(r) : "f"(x)); return r;
}

// ---------------- device scratch ----------------
__device__ float g_xw[(size_t)2 * ROWS * G4];
__device__ float g_UT[2 * G4 * HID];
__device__ float g_hT[2][2][HID][BATCH];
__device__ float g_hsum[2 * BATCH * HID];
__device__ unsigned g_flag[2][64][32];

// ---------------- init ----------------
__global__ void k_init() {
    int i = blockIdx.x * blockDim.x + threadIdx.x;
    float* p = &g_hT[0][0][0][0];
    if (i < 2 * 2 * HID * BATCH) p[i] = 0.f;
    if (i < 2 * 64 * 32) ((unsigned*)g_flag)[i] = 0u;
}

// ---------------- transpose U -> UT ----------------
__global__ void k_transpose(const float* __restrict__ Uf, const float* __restrict__ Ub) {
    int i = blockIdx.x * blockDim.x + threadIdx.x;
    if (i >= HID * G4) return;
    int k = i / G4, n = i % G4;
    g_UT[n * HID + k]            = Uf[i];
    g_UT[G4 * HID + n * HID + k] = Ub[i];
}

// ---------------- input GEMM v2: 128x96 tiles, cp.async double-buffered ----
#define BM 128
#define BN 96
#define GBK 12
#define NTILE 25              // DIM / GBK
__global__ __launch_bounds__(256, 2) void k_gemm(const float* __restrict__ X,
                       const float* __restrict__ Wf, const float* __restrict__ bf,
                       const float* __restrict__ Wb, const float* __restrict__ bb) {
    int dir = blockIdx.z;
    const float* W    = dir ? Wb : Wf;
    const float* bias = dir ? bb : bf;
    int m0 = blockIdx.y * BM;
    int n0 = blockIdx.x * BN;

    __shared__ __align__(16) float As[2][BM][GBK];   // [buf][row][kk]
    __shared__ __align__(16) float Bs[2][GBK][BN];   // [buf][kk][col]

    int tid = threadIdx.x;
    int tx = tid & 15;            // 16 n-groups of 6
    int ty = tid >> 4;            // 16 m-groups of 8

    unsigned asb = (unsigned)__cvta_generic_to_shared(&As[0][0][0]);
    unsigned bsb = (unsigned)__cvta_generic_to_shared(&Bs[0][0][0]);

    // stage k-tile t into buffer buf
    auto stage = [&](int t, int buf) {
        int k0 = t * GBK;
        // A: 384 float4 (128 rows x 3)
        #pragma unroll
        for (int l = 0; l < 2; ++l) {
            int idx = tid + l * 256;
            if (idx < BM * 3) {
                int row = idx / 3, f4 = idx % 3;
                unsigned dst = asb + (buf * BM * GBK + row * GBK + f4 * 4) * 4;
                const float* src = X + (size_t)(m0 + row) * DIM + k0 + f4 * 4;
                asm volatile("cp.async.cg.shared.global [%0], [%1], 16;"
                             :: "r"(dst), "l"(src));
            }
        }
        // B: 288 float4 (12 rows x 24)
        #pragma unroll
        for (int l = 0; l < 2; ++l) {
            int idx = tid + l * 256;
            if (idx < GBK * 24) {
                int kk = idx / 24, c4 = idx % 24;
                unsigned dst = bsb + (buf * GBK * BN + kk * BN + c4 * 4) * 4;
                const float* src = W + (size_t)(k0 + kk) * G4 + n0 + c4 * 4;
                asm volatile("cp.async.cg.shared.global [%0], [%1], 16;"
                             :: "r"(dst), "l"(src));
            }
        }
        asm volatile("cp.async.commit_group;" ::: "memory");
    };

    u64 acc[8][3] = {};           // [m-row][n-pair]

    stage(0, 0);
    for (int t = 0; t < NTILE; ++t) {
        int cur = t & 1;
        if (t + 1 < NTILE) {
            stage(t + 1, cur ^ 1);
            asm volatile("cp.async.wait_group 1;" ::: "memory");
        } else {
            asm volatile("cp.async.wait_group 0;" ::: "memory");
        }
        __syncthreads();

        #pragma unroll
        for (int kk = 0; kk < GBK; ++kk) {
            u64 bv0 = *(const u64*)&Bs[cur][kk][tx * 6];
            u64 bv1 = *(const u64*)&Bs[cur][kk][tx * 6 + 2];
            u64 bv2 = *(const u64*)&Bs[cur][kk][tx * 6 + 4];
            #pragma unroll
            for (int i = 0; i < 8; ++i) {
                float av = As[cur][ty * 8 + i][kk];
                u64 ap = pack2(av, av);
                ffma2(acc[i][0], ap, bv0);
                ffma2(acc[i][1], ap, bv1);
                ffma2(acc[i][2], ap, bv2);
            }
        }
        __syncthreads();
    }

    // epilogue: add bias, store as float2
    float bv[6];
    #pragma unroll
    for (int j = 0; j < 6; ++j) bv[j] = __ldg(&bias[n0 + tx * 6 + j]);
    float* outp = g_xw + (size_t)dir * ROWS * G4;
    #pragma unroll
    for (int i = 0; i < 8; ++i) {
        int row = m0 + ty * 8 + i;
        float2* o = (float2*)(outp + (size_t)row * G4 + n0 + tx * 6);
        #pragma unroll
        for (int j = 0; j < 3; ++j) {
            float lo, hi; unpack2(acc[i][j], lo, hi);
            o[j] = make_float2(lo + bv[2 * j], hi + bv[2 * j + 1]);
        }
    }
}

// ---------------- xw prefetch for one (b, jj) cell ----------------
__device__ __forceinline__ void load_xw4(float* px, int s, int b, int jj,
                                         int dir, int j0, int L) {
    bool active = (dir == 0) ? (s < SEQ) : (s < L);
    if (!active) return;
    int trow = (dir == 0) ? s : (L - 1 - s);
    const float* xwr = g_xw + ((size_t)dir * ROWS + b * SEQ + trow) * G4 + (j0 + jj);
    px[0] = __ldg(xwr);
    px[1] = __ldg(xwr + HID);
    px[2] = __ldg(xwr + 2 * HID);
    px[3] = __ldg(xwr + 3 * HID);
}

// ---------------- gate math for one (b, jj) cell ----------------
__device__ __forceinline__ void gate_cell(const float* __restrict__ z_sh,
                                          const float* __restrict__ px,
                                          int b, int jj, int dir, int j0,
                                          int s, int L, int rp,
                                          float& cr, float& hs) {
    float z0 = 0.f, z1 = 0.f, z2 = 0.f, z3 = 0.f;
    #pragma unroll
    for (int p = 0; p < KSPLIT; p++) {
        const float* zb = z_sh + (p * 64 + b) * ZPAD;
        z0 += zb[jj];
        z1 += zb[NJ + jj];
        z2 += zb[2 * NJ + jj];
        z3 += zb[3 * NJ + jj];
    }
    bool active = (dir == 0) ? true : (s < L);
    if (!active) return;
    float ig = fast_sigmoid(z0 + px[0]);
    float fg = fast_sigmoid(z1 + px[1]);
    float gg = fast_tanh(z2 + px[2]);
    float og = fast_sigmoid(z3 + px[3]);
    cr = fg * cr + ig * gg;
    float h = og * fast_tanh(cr);
    __stcg(&g_hT[rp ^ 1][dir][j0 + jj][b], h);
    if (dir == 1 || s < L) hs += h;
}

// ---------------- poll producer flag, then stage one 64B h slice ----------------
__device__ __forceinline__ void stage_chunk(unsigned h_base, const char* hsrc,
                                            int ck, int tid,
                                            const unsigned* flags, int myblk,
                                            unsigned tgt) {
    int prod = (ck * KC + (tid >> 2)) / NJ;
    if (prod != myblk) {
        const unsigned* fp = flags + prod * 32;
        unsigned v;
        do {
            asm volatile("ld.acquire.gpu.global.u32 %0, [%1];"
                         : "=r"(v) : "l"(fp) : "memory");
        } while (v < tgt);
    }
    unsigned dst = h_base + ((ck & 1) ? CHUNKB : 0) + tid * 64;
    const char* src = hsrc + (size_t)ck * CHUNKB + tid * 64;
    asm volatile("cp.async.cg.shared.global [%0], [%1], 16;" :: "r"(dst),      "l"(src));
    asm volatile("cp.async.cg.shared.global [%0], [%1], 16;" :: "r"(dst + 16), "l"(src + 16));
    asm volatile("cp.async.cg.shared.global [%0], [%1], 16;" :: "r"(dst + 32), "l"(src + 32));
    asm volatile("cp.async.cg.shared.global [%0], [%1], 16;" :: "r"(dst + 48), "l"(src + 48));
    asm volatile("cp.async.commit_group;" ::: "memory");
}

// ---------------- persistent recurrence kernel (R11, unchanged) ----------------
__global__ __launch_bounds__(NT, 1) void k_persist(const int* __restrict__ lengths) {
    extern __shared__ __align__(16) float smem[];
    float* u_sh = smem;
    float* z_sh = smem + HID * NCOL;
    float* h_sh = z_sh + KSPLIT * 64 * ZPAD;

    int tid = threadIdx.x;
    int bx  = blockIdx.x;
    int dir = (bx >= HALFG) ? 1 : 0;
    int blk = dir ? bx - HALFG : bx;
    int j0  = blk * NJ;

    unsigned h_base = (unsigned)__cvta_generic_to_shared(h_sh);
    const unsigned* flags = &g_flag[dir][0][0];

    {
        const float* UT = g_UT + (size_t)dir * G4 * HID;
        for (int idx = tid; idx < NCOL * HID; idx += NT) {
            int c = idx / HID, k = idx % HID;
            int gcol = (c / NJ) * HID + j0 + (c % NJ);
            u_sh[k * NCOL + c] = UT[(size_t)gcol * HID + k];
        }
    }

    int kh = tid / 80;
    int r  = tid % 80;
    int bb = (r / 10) * 8;
    int cc = (r % 10) * 4;

    int b0c  = tid & 63;
    int jj0c = tid >> 6;
    int b1c  = (tid + NT) & 63;
    int jj1c = (tid + NT) >> 6;
    int L0 = __ldg(&lengths[b0c]);
    int L1 = (tid < 160) ? __ldg(&lengths[b1c]) : 0;
    float cr0 = 0.f, cr1 = 0.f, hs0 = 0.f, hs1 = 0.f;

    float px0[4], px1[4], nx0[4], nx1[4];
    load_xw4(px0, 0, b0c, jj0c, dir, j0, L0);
    if (tid < 160) load_xw4(px1, 0, b1c, jj1c, dir, j0, L1);

    __syncthreads();

    for (int s = 0; s < SEQ; s++) {
        int rp = s & 1;
        const char* hsrc = (const char*)(&g_hT[rp][dir][0][0]);
        unsigned tgt = (unsigned)s;

        stage_chunk(h_base, hsrc, 0, tid, flags, blk, tgt);
        asm volatile("cp.async.wait_group 0;" ::: "memory");
        __syncthreads();

        u64 acc2[4][4] = {};
        #pragma unroll
        for (int ck = 0; ck < NCHUNK; ck++) {
            if (ck < NCHUNK - 1)
                stage_chunk(h_base, hsrc, ck + 1, tid, flags, blk, tgt);

            const float* hp = h_sh + ((ck & 1) ? CHUNKF : 0) + (kh * KSUB) * 64 + bb;
            const float* up = u_sh + (ck * KC + kh * KSUB) * NCOL + cc;
            #pragma unroll 5
            for (int kk = 0; kk < KSUB; kk++) {
                float4 ha = *(const float4*)hp;
                float4 hb = *(const float4*)(hp + 4);
                hp += 64;
                float4 u4 = *(const float4*)up;
                up += NCOL;
                u64 hpair[4] = {pack2(ha.x, ha.y), pack2(ha.z, ha.w),
                                pack2(hb.x, hb.y), pack2(hb.z, hb.w)};
                u64 ub[4] = {pack2(u4.x, u4.x), pack2(u4.y, u4.y),
                             pack2(u4.z, u4.z), pack2(u4.w, u4.w)};
                #pragma unroll
                for (int i = 0; i < 4; i++)
                    #pragma unroll
                    for (int j = 0; j < 4; j++)
                        ffma2(acc2[i][j], hpair[i], ub[j]);
            }

            if (ck == NCHUNK - 1) {
                #pragma unroll
                for (int i = 0; i < 4; i++) {
                    float* zr0 = z_sh + ((kh * 64) + bb + 2 * i) * ZPAD + cc;
                    float* zr1 = zr0 + ZPAD;
                    #pragma unroll
                    for (int j = 0; j < 4; j++) {
                        float lo, hi; unpack2(acc2[i][j], lo, hi);
                        zr0[j] = lo; zr1[j] = hi;
                    }
                }
                load_xw4(nx0, s + 1, b0c, jj0c, dir, j0, L0);
                if (tid < 160) load_xw4(nx1, s + 1, b1c, jj1c, dir, j0, L1);
            } else {
                asm volatile("cp.async.wait_group 0;" ::: "memory");
            }
            __syncthreads();
        }

        gate_cell(z_sh, px0, b0c, jj0c, dir, j0, s, L0, rp, cr0, hs0);
        if (tid < 160) gate_cell(z_sh, px1, b1c, jj1c, dir, j0, s, L1, rp, cr1, hs1);
        #pragma unroll
        for (int q = 0; q < 4; q++) { px0[q] = nx0[q]; px1[q] = nx1[q]; }
        __syncthreads();

        if (tid == 0) {
            asm volatile("st.release.gpu.global.u32 [%0], %1;"
                         :: "l"(&g_flag[dir][blk][0]), "r"((unsigned)(s + 1)) : "memory");
        }
    }

    g_hsum[dir * BATCH * HID + b0c * HID + j0 + jj0c] = hs0;
    if (tid < 160)
        g_hsum[dir * BATCH * HID + b1c * HID + j0 + jj1c] = hs1;
}

// ---------------- finalize: mean over T ----------------
__global__ void k_final(float* __restrict__ out) {
    int i = blockIdx.x * blockDim.x + threadIdx.x;
    if (i >= BATCH * 2 * HID) return;
    int b = i / (2 * HID), j = i % (2 * HID);
    float v = (j < HID) ? g_hsum[b * HID + j]
                        : g_hsum[BATCH * HID + b * HID + (j - HID)];
    out[i] = v * (1.0f / SEQ);
}

// ---------------- launch ----------------
extern "C" void kernel_launch(void* const* d_in, const int* in_sizes, int n_in,
                              void* d_out, int out_size) {
    const float *X = nullptr, *Wf = nullptr, *Uf = nullptr, *bf = nullptr;
    const float *Wb = nullptr, *Ub = nullptr, *bb = nullptr;
    const int* lengths = nullptr;
    int cW = 0, cU = 0, cb = 0;
    for (int i = 0; i < n_in; i++) {
        int s = in_sizes[i];
        if      (s == BATCH * SEQ * DIM) X = (const float*)d_in[i];
        else if (s == BATCH)             lengths = (const int*)d_in[i];
        else if (s == DIM * G4)   { if (cW++ == 0) Wf = (const float*)d_in[i]; else Wb = (const float*)d_in[i]; }
        else if (s == HID * G4)   { if (cU++ == 0) Uf = (const float*)d_in[i]; else Ub = (const float*)d_in[i]; }
        else if (s == G4)         { if (cb++ == 0) bf = (const float*)d_in[i]; else bb = (const float*)d_in[i]; }
    }

    static const int smem_bytes =
        (HID * NCOL + KSPLIT * 64 * ZPAD + 2 * KC * 64) * 4;   // 221952
    cudaFuncSetAttribute(k_persist, cudaFuncAttributeMaxDynamicSharedMemorySize, smem_bytes);

    k_init<<<(2 * 2 * HID * BATCH + 255) / 256, 256>>>();
    k_transpose<<<(HID * G4 + 255) / 256, 256>>>(Uf, Ub);
    k_gemm<<<dim3(G4 / BN, ROWS / BM, 2), 256>>>(X, Wf, bf, Wb, bb);
    k_persist<<<GRID_P, NT, smem_bytes>>>(lengths);
    k_final<<<(BATCH * 2 * HID + 255) / 256, 256>>>((float*)d_out);
}